// round 14
// baseline (speedup 1.0000x reference)
#include <cuda_runtime.h>
#include <math.h>

// ---------------------------------------------------------------------------
// QRNN: h_t = tanh(x_t @ Wh + b + h_{t-1} @ Uh),  T=512, B=32, D=1024
// Mega-kernel, warp-specialized:
//   warps 0-7  (256 thr): R12 recurrence consumer (h-GEMM, global flag sync)
//   warps 8-11 (128 thr): wh producer for THIS CTA's tile, 4 timesteps per
//                         block, delivered via a 2-slot SMEM ring.
// wh never touches global memory; no separate SGEMM kernel.
// ---------------------------------------------------------------------------

#define TT 512
#define BB 32
#define DD 1024
#define QQ 256

// smem float offsets
#define OFF_US    0                          // [1024][32]      32768
#define OFF_HS    32768                      // [8][1036]        8288
#define OFF_PART  41056                      // [8][264]         2112
#define OFF_XS    43168                      // [4][8][132]      4224
#define OFF_WHB   47392                      // [128][32]        4096
#define OFF_RING  51488                      // [2][4][8][32]    2048
#define OFF_FLAGS 53536                      // pdone[2], cdone[2]
#define SMEM_FLOATS 53544                    // 214176 B

#define HS_STRIDE 1036
#define PART_STRIDE 264

#define BAR1() asm volatile("bar.sync 1, 256;" ::: "memory")
#define BAR2() asm volatile("bar.sync 2, 128;" ::: "memory")

__device__ float g_Wh[DD * DD];
__device__ float g_Uh[DD * DD];
__device__ int   g_done[TT][4][32];   // per (t, batch-group, ntile) flag

// ------------------------- sync primitives ----------------------------------
__device__ __forceinline__ int ld_acq(const int* p) {
    int v;
    asm volatile("ld.acquire.gpu.global.s32 %0, [%1];" : "=r"(v) : "l"(p) : "memory");
    return v;
}
__device__ __forceinline__ void st_rel(int* p, int v) {
    asm volatile("st.release.gpu.global.s32 [%0], %1;" :: "l"(p), "r"(v) : "memory");
}

// --------------------------- quaternion matrix build ------------------------
// which==0 also zeroes the flag array.
__global__ void build_qmat_kernel(const float* __restrict__ wr,
                                  const float* __restrict__ wi,
                                  const float* __restrict__ wj,
                                  const float* __restrict__ wk,
                                  int which) {
    int e = blockIdx.x * blockDim.x + threadIdx.x;
    int d = blockIdx.y;
    if (which == 0 && d == 0) {
        for (int i = e; i < TT * 4 * 32; i += 1024)
            (&g_done[0][0][0])[i] = 0;
    }
    int br = d >> 8, bc = e >> 8;
    int r = d & 255, c = e & 255;
    int comp = br ^ bc;
    int mask = (0x5390 >> (br * 4)) & 0xF;
    float s = ((mask >> bc) & 1) ? -1.0f : 1.0f;
    const float* w = (comp == 0) ? wr : (comp == 1) ? wi : (comp == 2) ? wj : wk;
    float* W = which ? g_Uh : g_Wh;
    W[d * DD + e] = s * w[r * QQ + c];
}

// --------------------------- fused mega-kernel -------------------------------
__global__ void __launch_bounds__(384)
recur_kernel(float* __restrict__ out, const float* __restrict__ x,
             const float* __restrict__ bias) {
    extern __shared__ float sm[];
    float* Us   = sm + OFF_US;
    float* hs   = sm + OFF_HS;
    float* part = sm + OFF_PART;
    float* xs   = sm + OFF_XS;      // [4 t'][8 r][132]
    float* whb  = sm + OFF_WHB;     // [128 k][32 c]
    float* ring = sm + OFF_RING;    // [2 slot][4 t'][8 r][32 c]
    volatile int* pdone = (volatile int*)(sm + OFF_FLAGS);      // [2]
    volatile int* cdone = (volatile int*)(sm + OFF_FLAGS) + 2;  // [2]

    int tid = threadIdx.x;
    int n = blockIdx.x >> 2;        // ntile 0..31
    int g = blockIdx.x & 3;         // batch group 0..3

    // ---- all 384 threads: load Uh slab, init flags, one full-CTA sync ----
    for (int i = tid; i < 8192; i += 384) {               // 8192 float4
        int k = i >> 3, c4 = (i & 7) << 2;
        *(float4*)&Us[k * 32 + c4] =
            *(const float4*)&g_Uh[(size_t)k * DD + n * 32 + c4];
    }
    if (tid == 0) { pdone[0] = 0; pdone[1] = 0; cdone[0] = 0; cdone[1] = 0; }
    __syncthreads();

    // ======================= PRODUCER (warps 8-11) ==========================
    if (tid >= 256) {
        int plane = tid - 256;                // 0..127
        int c4p = plane & 7;                  // col group (4 cols)
        int rp  = (plane >> 3) & 7;           // row 0..7
        int t2  = plane >> 6;                 // 0..1 -> t' pair {2t2, 2t2+1}

        float biasr[4];
#pragma unroll
        for (int j = 0; j < 4; ++j) biasr[j] = bias[n * 32 + c4p * 4 + j];

        const float* xp0 = &xs[(2 * t2) * 1056 + rp * 132];
        const float* wpp = &whb[c4p * 4];

        for (int tb = 0; tb < 128; ++tb) {
            float acc0[4], acc1[4];
#pragma unroll
            for (int j = 0; j < 4; ++j) { acc0[j] = biasr[j]; acc1[j] = biasr[j]; }

            for (int chunk = 0; chunk < 8; ++chunk) {
                // stage xs: 4 t' x 8 r x 128 k  (1024 float4)
                for (int m = plane; m < 1024; m += 128) {
                    int i2 = m >> 8;                 // t' 0..3
                    int rr = (m >> 5) & 7;           // r
                    int k4 = (m & 31) << 2;          // k offset
                    *(float4*)&xs[i2 * 1056 + rr * 132 + k4] =
                        *(const float4*)&x[(size_t)(tb * 4 + i2) * (BB * DD)
                                           + (size_t)(g * 8 + rr) * DD
                                           + chunk * 128 + k4];
                }
                // stage whb: 128 k x 32 c  (1024 float4)
                for (int m = plane; m < 1024; m += 128) {
                    int kk = m >> 3, cc = (m & 7) << 2;
                    *(float4*)&whb[kk * 32 + cc] =
                        *(const float4*)&g_Wh[(size_t)(chunk * 128 + kk) * DD
                                              + n * 32 + cc];
                }
                BAR2();

#pragma unroll 4
                for (int kk = 0; kk < 128; kk += 4) {
                    float xa[4], xb[4];
                    *(float4*)xa = *(const float4*)&xp0[kk];
                    *(float4*)xb = *(const float4*)&xp0[1056 + kk];
#pragma unroll
                    for (int q = 0; q < 4; ++q) {
                        float wv[4];
                        *(float4*)wv = *(const float4*)&wpp[(kk + q) * 32];
#pragma unroll
                        for (int j = 0; j < 4; ++j) {
                            acc0[j] += xa[q] * wv[j];
                            acc1[j] += xb[q] * wv[j];
                        }
                    }
                }
                BAR2();                      // before restaging next chunk
            }

            int slot = tb & 1;
            // backpressure: ensure block tb-2 (same slot) fully consumed
            if (tb >= 2) {
                if (plane < 32) {            // warp 8 spins convergently
                    int r2;
                    do { r2 = (cdone[slot] >= tb - 1); }
                    while (!__all_sync(0xffffffffu, r2));
                }
                BAR2();
            }
            // publish wh block to ring
            int base = slot * 1024 + (2 * t2) * 256 + rp * 32 + c4p * 4;
            *(float4*)&ring[base]       = *(float4*)acc0;
            *(float4*)&ring[base + 256] = *(float4*)acc1;
            BAR2();
            if (plane == 0) { __threadfence_block(); pdone[slot] = tb + 1; }
        }
        return;   // producers exit
    }

    // ======================= CONSUMER (warps 0-7) ===========================
    int ob = tid >> 5, oc = tid & 31;
    size_t obase = (size_t)(g * 8 + ob) * DD + n * 32 + oc;
    int lane = tid & 31, w = tid >> 5;
    int bg = (lane >> 3) << 1;
    int cg = (lane & 7) << 2;
    const int kbase = w << 7;

    // t = 0: wait for producer block 0, h0 = tanh(wh[0])
    if (w == 0) {
        int r2;
        do { r2 = (pdone[0] >= 1); } while (!__all_sync(0xffffffffu, r2));
    }
    BAR1();
    out[obase] = tanhf(ring[ob * 32 + oc]);   // slot 0, t'=0
    BAR1();
    if (tid == 0) st_rel(&g_done[0][g][n], 1);

    for (int t = 1; t < TT; ++t) {
        int tb = t >> 2, slot = tb & 1, tq = t & 3;

        // poll: warp0 lanes watch 32 h-flags; lane0 also requires wh block
        if (w == 0) {
            const int* fp = &g_done[t - 1][g][lane];
            int rdy;
            do {
                rdy = (ld_acq(fp) != 0);
                if (lane == 0 && pdone[slot] < tb + 1) rdy = 0;
            } while (!__all_sync(0xffffffffu, rdy));
        }
        BAR1();

        float whv = ring[slot * 1024 + tq * 256 + ob * 32 + oc];

        // per-warp private stage: 8 rows x this warp's 128-k slice
        {
            const float* hrow = out + (size_t)(t - 1) * BB * DD
                              + (size_t)(g * 8) * DD + kbase;
            float4 v[8];
#pragma unroll
            for (int j = 0; j < 8; ++j)
                v[j] = __ldcg((const float4*)&hrow[(size_t)j * DD + (lane << 2)]);
#pragma unroll
            for (int j = 0; j < 8; ++j)
                *(float4*)&hs[j * HS_STRIDE + kbase + (lane << 2)] = v[j];
        }
        __syncwarp();

        float a0[4] = {0.f, 0.f, 0.f, 0.f};
        float a1[4] = {0.f, 0.f, 0.f, 0.f};
        const float* h0p = &hs[bg * HS_STRIDE + kbase];
        const float* h1p = &hs[(bg + 1) * HS_STRIDE + kbase];
        const float* up  = &Us[kbase * 32 + cg];

#pragma unroll 4
        for (int kk = 0; kk < 128; kk += 4) {
            float h0v[4], h1v[4];
            *(float4*)h0v = *(const float4*)&h0p[kk];
            *(float4*)h1v = *(const float4*)&h1p[kk];
#pragma unroll
            for (int q = 0; q < 4; q++) {
                float uv[4];
                *(float4*)uv = *(const float4*)&up[(kk + q) * 32];
#pragma unroll
                for (int j = 0; j < 4; j++) {
                    a0[j] += h0v[q] * uv[j];
                    a1[j] += h1v[q] * uv[j];
                }
            }
        }

        // intra-CTA split-K reduce (fixed order => deterministic)
        *(float4*)&part[w * PART_STRIDE + bg * 32 + cg]       = *(float4*)a0;
        *(float4*)&part[w * PART_STRIDE + (bg + 1) * 32 + cg] = *(float4*)a1;
        BAR1();

        // last step of a wh block: mark ring slot consumed (all reads done)
        if (tq == 3 && tid == 0) cdone[slot] = tb + 1;

        float s = whv;
#pragma unroll
        for (int ww = 0; ww < 8; ww++) s += part[ww * PART_STRIDE + tid];
        out[(size_t)t * BB * DD + obase] = tanhf(s);

        BAR1();                                // all STGs issued before release
        if (t < TT - 1 && tid == 0) st_rel(&g_done[t][g][n], 1);
    }
}

// --------------------------- launch ------------------------------------------
extern "C" void kernel_launch(void* const* d_in, const int* in_sizes, int n_in,
                              void* d_out, int out_size) {
    const float* x    = (const float*)d_in[0];
    const float* wh_r = (const float*)d_in[1];
    const float* wh_i = (const float*)d_in[2];
    const float* wh_j = (const float*)d_in[3];
    const float* wh_k = (const float*)d_in[4];
    const float* uh_r = (const float*)d_in[5];
    const float* uh_i = (const float*)d_in[6];
    const float* uh_j = (const float*)d_in[7];
    const float* uh_k = (const float*)d_in[8];
    const float* wh_b = (const float*)d_in[9];
    float* out = (float*)d_out;

    dim3 bq(DD / 256, DD);
    build_qmat_kernel<<<bq, 256>>>(wh_r, wh_i, wh_j, wh_k, 0);  // also zeroes flags
    build_qmat_kernel<<<bq, 256>>>(uh_r, uh_i, uh_j, uh_k, 1);

    const int smem_bytes = SMEM_FLOATS * 4;   // ~214 KB
    cudaFuncSetAttribute(recur_kernel,
                         cudaFuncAttributeMaxDynamicSharedMemorySize, smem_bytes);
    recur_kernel<<<32 * 4, 384, smem_bytes>>>(out, x, wh_b);
}

// round 17
// speedup vs baseline: 1.5776x; 1.5776x over previous
#include <cuda_runtime.h>
#include <cuda_bf16.h>
#include <stdint.h>
#include <math.h>

// ---------------------------------------------------------------------------
// QRNN: h_t = tanh(x_t @ Wh + b + h_{t-1} @ Uh),  T=512, B=32, D=1024
// Phase B: split-bf16 tensor-core GEMM via mma.sync.m16n8k16 (compute_103-safe;
//          tcgen05 is rejected by ptxas on the harness's virtual arch).
//          wh = xhi*Whi + xhi*Wlo + xlo*Whi, fp32 accumulation.
// Phase C: R12 recurrence (proven).
// ---------------------------------------------------------------------------

#define TT 512
#define BB 32
#define DD 1024
#define QQ 256

#define HS_STRIDE 1036
#define PART_STRIDE 264

__device__ float g_Wh[DD * DD];
__device__ float g_Uh[DD * DD];
__device__ int   g_done[TT][4][32];
__device__ __nv_bfloat16 g_xhi[TT * BB * DD];
__device__ __nv_bfloat16 g_xlo[TT * BB * DD];
__device__ __nv_bfloat16 g_Whhi[DD * DD];   // [k][n]
__device__ __nv_bfloat16 g_Whlo[DD * DD];

// ------------------------- sync primitives ----------------------------------
__device__ __forceinline__ int ld_acq(const int* p) {
    int v;
    asm volatile("ld.acquire.gpu.global.s32 %0, [%1];" : "=r"(v) : "l"(p) : "memory");
    return v;
}
__device__ __forceinline__ void st_rel(int* p, int v) {
    asm volatile("st.release.gpu.global.s32 [%0], %1;" :: "l"(p), "r"(v) : "memory");
}
__device__ __forceinline__ uint32_t smem_u32(const void* p) {
    uint32_t a;
    asm("{ .reg .u64 t; cvta.to.shared.u64 t, %1; cvt.u32.u64 %0, t; }"
        : "=r"(a) : "l"(p));
    return a;
}

// ------------------------- mma helpers ---------------------------------------
__device__ __forceinline__ void ldsm_x4(uint32_t addr, uint32_t& r0, uint32_t& r1,
                                        uint32_t& r2, uint32_t& r3) {
    asm volatile("ldmatrix.sync.aligned.m8n8.x4.shared.b16 {%0,%1,%2,%3}, [%4];"
                 : "=r"(r0), "=r"(r1), "=r"(r2), "=r"(r3) : "r"(addr));
}
__device__ __forceinline__ void ldsm_x2t(uint32_t addr, uint32_t& r0, uint32_t& r1) {
    asm volatile("ldmatrix.sync.aligned.m8n8.x2.trans.shared.b16 {%0,%1}, [%2];"
                 : "=r"(r0), "=r"(r1) : "r"(addr));
}
__device__ __forceinline__ void mma_bf16(float* d, const uint32_t* a,
                                         const uint32_t* b) {
    asm volatile(
        "mma.sync.aligned.m16n8k16.row.col.f32.bf16.bf16.f32 "
        "{%0,%1,%2,%3}, {%4,%5,%6,%7}, {%8,%9}, {%0,%1,%2,%3};"
        : "+f"(d[0]), "+f"(d[1]), "+f"(d[2]), "+f"(d[3])
        : "r"(a[0]), "r"(a[1]), "r"(a[2]), "r"(a[3]), "r"(b[0]), "r"(b[1]));
}

// --------------------------- x split-bf16 conversion -------------------------
__global__ void convert_x_kernel(const float* __restrict__ x) {
    int i = (blockIdx.x * 256 + threadIdx.x) * 4;
    float4 v = *(const float4*)&x[i];
    __nv_bfloat16 h[4], l[4];
    float vv[4] = {v.x, v.y, v.z, v.w};
#pragma unroll
    for (int j = 0; j < 4; ++j) {
        h[j] = __float2bfloat16(vv[j]);
        l[j] = __float2bfloat16(vv[j] - __bfloat162float(h[j]));
    }
    *(uint2*)&g_xhi[i] = *(uint2*)h;
    *(uint2*)&g_xlo[i] = *(uint2*)l;
}

// --------------------------- quaternion matrix build ------------------------
// which==0 (Wh): also zero flags and write bf16 hi/lo split of Wh.
__global__ void build_qmat_kernel(const float* __restrict__ wr,
                                  const float* __restrict__ wi,
                                  const float* __restrict__ wj,
                                  const float* __restrict__ wk,
                                  int which) {
    int e = blockIdx.x * blockDim.x + threadIdx.x;
    int d = blockIdx.y;
    if (which == 0 && d == 0) {
        for (int i = e; i < TT * 4 * 32; i += 1024)
            (&g_done[0][0][0])[i] = 0;
    }
    int br = d >> 8, bc = e >> 8;
    int r = d & 255, c = e & 255;
    int comp = br ^ bc;
    int mask = (0x5390 >> (br * 4)) & 0xF;
    float s = ((mask >> bc) & 1) ? -1.0f : 1.0f;
    const float* w = (comp == 0) ? wr : (comp == 1) ? wi : (comp == 2) ? wj : wk;
    float val = s * w[r * QQ + c];
    if (which) {
        g_Uh[d * DD + e] = val;
    } else {
        g_Wh[d * DD + e] = val;
        __nv_bfloat16 hb = __float2bfloat16(val);
        g_Whhi[d * DD + e] = hb;
        g_Whlo[d * DD + e] = __float2bfloat16(val - __bfloat162float(hb));
    }
}

// --------------------------- mma.sync wh GEMM --------------------------------
// CTA: 256 thr = 8 warps (warp_m = wid&3, warp_n = wid>>2).
// Tile M=128 (blockIdx.y) x N=64 (blockIdx.x); K in 16 chunks of 64.
// SMEM: Ahi/Alo [128][72] bf16, Bhi/Blo [64][72] bf16 (B stored k-major).
#define AST 72
#define SM_AHI 0
#define SM_ALO (SM_AHI + 128 * AST * 2)          // 18432
#define SM_BHI (SM_ALO + 128 * AST * 2)          // 36864
#define SM_BLO (SM_BHI + 64 * AST * 2)           // 46080
#define SM_MMA_TOTAL (SM_BLO + 64 * AST * 2)     // 55296

__global__ void __launch_bounds__(256)
wh_gemm_kernel(float* __restrict__ out, const float* __restrict__ bias) {
    extern __shared__ char smc[];
    uint32_t sbase = smem_u32(smc);
    __nv_bfloat16* Ahi = (__nv_bfloat16*)(smc + SM_AHI);
    __nv_bfloat16* Alo = (__nv_bfloat16*)(smc + SM_ALO);
    __nv_bfloat16* Bhi = (__nv_bfloat16*)(smc + SM_BHI);
    __nv_bfloat16* Blo = (__nv_bfloat16*)(smc + SM_BLO);

    int tid = threadIdx.x;
    int lane = tid & 31, wid = tid >> 5;
    int warp_m = wid & 3, warp_n = wid >> 2;
    int n0 = blockIdx.x * 64;
    int m0 = blockIdx.y * 128;

    float acc[2][4][4];
#pragma unroll
    for (int mi = 0; mi < 2; ++mi)
#pragma unroll
        for (int ni = 0; ni < 4; ++ni)
#pragma unroll
            for (int j = 0; j < 4; ++j) acc[mi][ni][j] = 0.0f;

    // fragment addresses (fixed per thread, k-offset varies)
    int a_row = warp_m * 32 + (lane & 15);
    int a_colb = (lane >> 4) * 8;
    int b_krow = lane & 15;

    for (int chunk = 0; chunk < 16; ++chunk) {
        int k0 = chunk * 64;
        // stage A hi/lo: 1024 uint4 each, 4 per thread
#pragma unroll
        for (int i = 0; i < 4; ++i) {
            int u = tid + (i << 8);
            int r = u >> 3, c16 = (u & 7) << 3;
            size_t gi = (size_t)(m0 + r) * DD + k0 + c16;
            *(uint4*)&Ahi[r * AST + c16] = *(const uint4*)&g_xhi[gi];
            *(uint4*)&Alo[r * AST + c16] = *(const uint4*)&g_xlo[gi];
        }
        // stage B hi/lo: 512 uint4 each, 2 per thread
#pragma unroll
        for (int i = 0; i < 2; ++i) {
            int u = tid + (i << 8);
            int r = u >> 3, c16 = (u & 7) << 3;
            size_t gi = (size_t)(k0 + r) * DD + n0 + c16;
            *(uint4*)&Bhi[r * AST + c16] = *(const uint4*)&g_Whhi[gi];
            *(uint4*)&Blo[r * AST + c16] = *(const uint4*)&g_Whlo[gi];
        }
        __syncthreads();

#pragma unroll
        for (int ks = 0; ks < 4; ++ks) {
            int kk = ks * 16;
            uint32_t ah[2][4], al[2][4], bh[4][2], bl[4][2];
#pragma unroll
            for (int mi = 0; mi < 2; ++mi) {
                uint32_t off = (uint32_t)(((a_row + mi * 16) * AST + kk + a_colb) * 2);
                ldsm_x4(sbase + SM_AHI + off, ah[mi][0], ah[mi][1], ah[mi][2], ah[mi][3]);
                ldsm_x4(sbase + SM_ALO + off, al[mi][0], al[mi][1], al[mi][2], al[mi][3]);
            }
#pragma unroll
            for (int ni = 0; ni < 4; ++ni) {
                uint32_t off = (uint32_t)(((kk + b_krow) * AST
                                           + warp_n * 32 + ni * 8) * 2);
                ldsm_x2t(sbase + SM_BHI + off, bh[ni][0], bh[ni][1]);
                ldsm_x2t(sbase + SM_BLO + off, bl[ni][0], bl[ni][1]);
            }
#pragma unroll
            for (int mi = 0; mi < 2; ++mi)
#pragma unroll
                for (int ni = 0; ni < 4; ++ni) {
                    mma_bf16(acc[mi][ni], ah[mi], bh[ni]);
                    mma_bf16(acc[mi][ni], ah[mi], bl[ni]);
                    mma_bf16(acc[mi][ni], al[mi], bh[ni]);
                }
        }
        __syncthreads();
    }

    // epilogue: D fragment -> out (+bias)
    int gid = lane >> 2, c2 = (lane & 3) * 2;
#pragma unroll
    for (int mi = 0; mi < 2; ++mi) {
#pragma unroll
        for (int ni = 0; ni < 4; ++ni) {
            int col = n0 + warp_n * 32 + ni * 8 + c2;
            float b0 = bias[col], b1 = bias[col + 1];
            size_t row0 = (size_t)(m0 + warp_m * 32 + mi * 16 + gid) * DD + col;
            size_t row1 = row0 + 8 * DD;
            out[row0]     = acc[mi][ni][0] + b0;
            out[row0 + 1] = acc[mi][ni][1] + b1;
            out[row1]     = acc[mi][ni][2] + b0;
            out[row1 + 1] = acc[mi][ni][3] + b1;
        }
    }
}

// --------------------------- recurrence (R12, proven) ------------------------
__global__ void __launch_bounds__(256)
recur_kernel(float* __restrict__ out) {
    extern __shared__ float sm[];
    float* Us   = sm;
    float* hs   = Us + 1024 * 32;
    float* part = hs + 8 * HS_STRIDE;

    int tid = threadIdx.x;
    int n = blockIdx.x >> 2;
    int g = blockIdx.x & 3;

    for (int i = tid; i < 1024 * 8; i += 256) {
        int k = i >> 3, c4 = (i & 7) << 2;
        *(float4*)&Us[k * 32 + c4] =
            *(const float4*)&g_Uh[(size_t)k * DD + n * 32 + c4];
    }

    int ob = tid >> 5, oc = tid & 31;
    size_t obase = (size_t)(g * 8 + ob) * DD + n * 32 + oc;

    float v0 = out[obase];
    __syncthreads();
    out[obase] = tanhf(v0);
    __syncthreads();
    if (tid == 0) st_rel(&g_done[0][g][n], 1);

    int lane = tid & 31, w = tid >> 5;
    int bg = (lane >> 3) << 1;
    int cg = (lane & 7) << 2;
    const int kbase = w << 7;

    for (int t = 1; t < TT; ++t) {
        float whv = __ldcg(&out[(size_t)t * BB * DD + obase]);

        if (w == 0) {
            const int* fp = &g_done[t - 1][g][lane];
            int rdy = (ld_acq(fp) != 0);
            while (!__all_sync(0xffffffffu, rdy)) {
                if (!rdy) rdy = (ld_acq(fp) != 0);
            }
        }
        __syncthreads();

        {
            const float* hrow = out + (size_t)(t - 1) * BB * DD
                              + (size_t)(g * 8) * DD + kbase;
            float4 v[8];
#pragma unroll
            for (int j = 0; j < 8; ++j)
                v[j] = __ldcg((const float4*)&hrow[(size_t)j * DD + (lane << 2)]);
#pragma unroll
            for (int j = 0; j < 8; ++j)
                *(float4*)&hs[j * HS_STRIDE + kbase + (lane << 2)] = v[j];
        }
        __syncwarp();

        float a0[4] = {0.f, 0.f, 0.f, 0.f};
        float a1[4] = {0.f, 0.f, 0.f, 0.f};
        const float* h0p = &hs[bg * HS_STRIDE + kbase];
        const float* h1p = &hs[(bg + 1) * HS_STRIDE + kbase];
        const float* up  = &Us[kbase * 32 + cg];

#pragma unroll 4
        for (int kk = 0; kk < 128; kk += 4) {
            float h0v[4], h1v[4];
            *(float4*)h0v = *(const float4*)&h0p[kk];
            *(float4*)h1v = *(const float4*)&h1p[kk];
#pragma unroll
            for (int q = 0; q < 4; q++) {
                float uv[4];
                *(float4*)uv = *(const float4*)&up[(kk + q) * 32];
#pragma unroll
                for (int j = 0; j < 4; j++) {
                    a0[j] += h0v[q] * uv[j];
                    a1[j] += h1v[q] * uv[j];
                }
            }
        }

        *(float4*)&part[w * PART_STRIDE + bg * 32 + cg]       = *(float4*)a0;
        *(float4*)&part[w * PART_STRIDE + (bg + 1) * 32 + cg] = *(float4*)a1;
        __syncthreads();

        float s = whv;
#pragma unroll
        for (int ww = 0; ww < 8; ww++) s += part[ww * PART_STRIDE + tid];
        out[(size_t)t * BB * DD + obase] = tanhf(s);

        __syncthreads();
        if (t < TT - 1 && tid == 0) st_rel(&g_done[t][g][n], 1);
    }
}

// --------------------------- launch ------------------------------------------
extern "C" void kernel_launch(void* const* d_in, const int* in_sizes, int n_in,
                              void* d_out, int out_size) {
    const float* x    = (const float*)d_in[0];
    const float* wh_r = (const float*)d_in[1];
    const float* wh_i = (const float*)d_in[2];
    const float* wh_j = (const float*)d_in[3];
    const float* wh_k = (const float*)d_in[4];
    const float* uh_r = (const float*)d_in[5];
    const float* uh_i = (const float*)d_in[6];
    const float* uh_j = (const float*)d_in[7];
    const float* uh_k = (const float*)d_in[8];
    const float* wh_b = (const float*)d_in[9];
    float* out = (float*)d_out;

    dim3 bq(DD / 256, DD);
    build_qmat_kernel<<<bq, 256>>>(wh_r, wh_i, wh_j, wh_k, 0);
    build_qmat_kernel<<<bq, 256>>>(uh_r, uh_i, uh_j, uh_k, 1);

    convert_x_kernel<<<(TT * BB * DD) / 1024, 256>>>(x);

    cudaFuncSetAttribute(wh_gemm_kernel,
                         cudaFuncAttributeMaxDynamicSharedMemorySize, SM_MMA_TOTAL);
    dim3 gg(DD / 64, (TT * BB) / 128);   // (16, 128)
    wh_gemm_kernel<<<gg, 256, SM_MMA_TOTAL>>>(out, wh_b);

    const int smem_bytes = (1024 * 32 + 8 * HS_STRIDE + 8 * PART_STRIDE) * 4;
    cudaFuncSetAttribute(recur_kernel,
                         cudaFuncAttributeMaxDynamicSharedMemorySize, smem_bytes);
    recur_kernel<<<32 * 4, 256, smem_bytes>>>(out);
}